// round 15
// baseline (speedup 1.0000x reference)
#include <cuda_runtime.h>
#include <cuda_bf16.h>
#include <cuda_fp16.h>
#include <cstdint>

#define D_MODEL 1024
#define N_HEADS 16
#define DK      64
#define B_SIZE  2
#define S_LEN   2048
#define M_ROWS  (B_SIZE * S_LEN)   // 4096
#define BHS     (B_SIZE * N_HEADS * S_LEN)

// ---------------- scratch ----------------
__device__ __half g_Af[3][(size_t)M_ROWS * D_MODEL];           // activations fp16 (q,k,v)
__device__ __half g_Wth[3][(size_t)D_MODEL * D_MODEL];         // W^T hi fp16 [n][k] (q,k,v)
__device__ __half g_Wtl[3][(size_t)D_MODEL * D_MODEL];         // W^T lo fp16 [n][k]
__device__ __half g_Wtf[(size_t)D_MODEL * D_MODEL];            // Wo^T fp16 [n][k]

// attention operands (fp16)
__device__ __half g_Qf[(size_t)M_ROWS * D_MODEL];              // [B,H,S,DK], scaled 1/8
__device__ __half g_Kf[(size_t)M_ROWS * D_MODEL];              // [B,H,S,DK] (K + kpe)
__device__ __half g_Vf[(size_t)M_ROWS * D_MODEL];              // [B,H,S,DK]
__device__ __half g_Of[(size_t)M_ROWS * D_MODEL];              // attn out [B,S,D] fp16

// split-K attention partials
__device__ float  g_Opart[2][(size_t)BHS * DK];
__device__ float2 g_MLpart[2][BHS];

// ======================= helpers =======================
__device__ __forceinline__ uint32_t smem_u32(const void* p) {
    uint32_t a;
    asm("{ .reg .u64 t; cvta.to.shared.u64 t, %1; cvt.u32.u64 %0, t; }" : "=r"(a) : "l"(p));
    return a;
}
__device__ __forceinline__ void cp16(uint32_t dst, const void* src) {
    asm volatile("cp.async.cg.shared.global [%0], [%1], 16;" :: "r"(dst), "l"(src));
}
__device__ __forceinline__ void ldsm_x4(uint32_t& r0, uint32_t& r1, uint32_t& r2, uint32_t& r3, uint32_t addr) {
    asm volatile("ldmatrix.sync.aligned.m8n8.x4.shared.b16 {%0,%1,%2,%3}, [%4];"
        : "=r"(r0), "=r"(r1), "=r"(r2), "=r"(r3) : "r"(addr));
}
__device__ __forceinline__ void ldsm_x4_t(uint32_t& r0, uint32_t& r1, uint32_t& r2, uint32_t& r3, uint32_t addr) {
    asm volatile("ldmatrix.sync.aligned.m8n8.x4.trans.shared.b16 {%0,%1,%2,%3}, [%4];"
        : "=r"(r0), "=r"(r1), "=r"(r2), "=r"(r3) : "r"(addr));
}
__device__ __forceinline__ void ldsm_x2(uint32_t& r0, uint32_t& r1, uint32_t addr) {
    asm volatile("ldmatrix.sync.aligned.m8n8.x2.shared.b16 {%0,%1}, [%2];"
        : "=r"(r0), "=r"(r1) : "r"(addr));
}
__device__ __forceinline__ void mma_f16(float* c, const uint32_t* a, uint32_t b0, uint32_t b1) {
    asm volatile("mma.sync.aligned.m16n8k16.row.col.f32.f16.f16.f32 "
        "{%0,%1,%2,%3}, {%4,%5,%6,%7}, {%8,%9}, {%0,%1,%2,%3};"
        : "+f"(c[0]), "+f"(c[1]), "+f"(c[2]), "+f"(c[3])
        : "r"(a[0]), "r"(a[1]), "r"(a[2]), "r"(a[3]), "r"(b0), "r"(b1));
}
__device__ __forceinline__ uint32_t pack_h2(float a, float b) {
    __half2 t = __floats2half2_rn(a, b);
    return *(uint32_t*)&t;
}

// ======================= prep kernels =======================
__global__ __launch_bounds__(256) void cvt_qkv_kernel(
    const float* __restrict__ q, const float* __restrict__ k, const float* __restrict__ v)
{
    int z = blockIdx.y;
    const float* src = (z == 0) ? q : (z == 1) ? k : v;
    __half* dst = g_Af[z];
    size_t i = ((size_t)blockIdx.x * 256 + threadIdx.x) * 4;
    float4 a = *(const float4*)(src + i);
    *(__half2*)(dst + i)     = __floats2half2_rn(a.x, a.y);
    *(__half2*)(dst + i + 2) = __floats2half2_rn(a.z, a.w);
}

__global__ void splitW_kernel(
    const float* __restrict__ Wq, const float* __restrict__ Wk,
    const float* __restrict__ Wv, const float* __restrict__ Wo)
{
    __shared__ float sm[32][33];
    int z = blockIdx.z;
    const float* W = (z == 0) ? Wq : (z == 1) ? Wk : (z == 2) ? Wv : Wo;
    int n0 = blockIdx.x * 32, k0 = blockIdx.y * 32;
    int tx = threadIdx.x, ty = threadIdx.y;
#pragma unroll
    for (int i = 0; i < 4; i++)
        sm[ty + 8 * i][tx] = W[(size_t)(k0 + ty + 8 * i) * D_MODEL + n0 + tx];
    __syncthreads();
#pragma unroll
    for (int i = 0; i < 4; i++) {
        int c = ty + 8 * i;
        float vv = sm[tx][c];
        size_t o = (size_t)(n0 + c) * D_MODEL + k0 + tx;
        if (z < 3) {
            __half h = __float2half_rn(vv);
            g_Wth[z][o] = h;
            g_Wtl[z][o] = __float2half_rn(vv - __half2float(h));
        } else {
            g_Wtf[o] = __float2half_rn(vv);
        }
    }
}

// ======================= 2-pass fp16 GEMM (Q/K/V proj): C = A*(Wh + Wl) =======================
#define BM 128
#define BN 128
#define KSTRIDE 40
#define G_TILE_B (128 * KSTRIDE * 2)       // 10240
#define P_STAGE_B (3 * G_TILE_B)           // A + Wh + Wl = 30720
#define GEMM_SMEM (2 * P_STAGE_B)          // 61440

__global__ __launch_bounds__(256)
void gemm_f16_kernel(const float* __restrict__ kpe,
                     const float* __restrict__ bq, const float* __restrict__ bk,
                     const float* __restrict__ bv)
{
    extern __shared__ char sgem[];
    const uint32_t sbase = smem_u32(sgem);

    const int z = blockIdx.z;
    const __half* Ap  = g_Af[z];
    const __half* Whp = g_Wth[z];
    const __half* Wlp = g_Wtl[z];
    const float* bias = (z == 0) ? bq : (z == 1) ? bk : bv;

    const int m0 = blockIdx.y * BM;
    const int n0 = blockIdx.x * BN;
    const int tid = threadIdx.x;
    const int wid = tid >> 5, lane = tid & 31;
    const int wm = wid & 1, wn = wid >> 1;

    const int lrow = tid >> 1, lcp = tid & 1;

    auto load_chunk = [&](int kc, int buf) {
        const size_t ga = (size_t)(m0 + lrow) * D_MODEL + kc * 32 + lcp * 16;
        const size_t gb = (size_t)(n0 + lrow) * D_MODEL + kc * 32 + lcp * 16;
        const uint32_t so = sbase + buf * P_STAGE_B + (lrow * KSTRIDE + lcp * 16) * 2;
        cp16(so,                Ap + ga);  cp16(so + 16,                Ap + ga + 8);
        cp16(so + G_TILE_B,     Whp + gb); cp16(so + G_TILE_B + 16,     Whp + gb + 8);
        cp16(so + 2 * G_TILE_B, Wlp + gb); cp16(so + 2 * G_TILE_B + 16, Wlp + gb + 8);
        asm volatile("cp.async.commit_group;" ::: "memory");
    };

    float acc[4][4][4];
#pragma unroll
    for (int i = 0; i < 4; i++)
#pragma unroll
        for (int j = 0; j < 4; j++)
#pragma unroll
            for (int c = 0; c < 4; c++) acc[i][j][c] = 0.f;

    load_chunk(0, 0);
    load_chunk(1, 1);

    const int a_row = (lane & 15), a_koff = (lane >> 4) * 8;
    const int b_row = (lane & 7),  b_koff = ((lane >> 3) & 1) * 8;

    for (int c = 0; c < 32; c++) {
        const int buf = c & 1;
        if (c < 31) asm volatile("cp.async.wait_group 1;" ::: "memory");
        else        asm volatile("cp.async.wait_group 0;" ::: "memory");
        __syncthreads();

        const uint32_t st = sbase + buf * P_STAGE_B;
#pragma unroll
        for (int k16 = 0; k16 < 2; k16++) {
            uint32_t a[4][4], bh[4][2];
#pragma unroll
            for (int mi = 0; mi < 4; mi++)
                ldsm_x4(a[mi][0], a[mi][1], a[mi][2], a[mi][3],
                        st + ((wm * 64 + mi * 16 + a_row) * KSTRIDE + k16 * 16 + a_koff) * 2);
#pragma unroll
            for (int ni = 0; ni < 4; ni++)
                ldsm_x2(bh[ni][0], bh[ni][1],
                        st + G_TILE_B + ((wn * 32 + ni * 8 + b_row) * KSTRIDE + k16 * 16 + b_koff) * 2);
#pragma unroll
            for (int ni = 0; ni < 4; ni++)
#pragma unroll
                for (int mi = 0; mi < 4; mi++)
                    mma_f16(acc[mi][ni], a[mi], bh[ni][0], bh[ni][1]);
            {
                uint32_t bl[4][2];
#pragma unroll
                for (int ni = 0; ni < 4; ni++)
                    ldsm_x2(bl[ni][0], bl[ni][1],
                            st + 2 * G_TILE_B + ((wn * 32 + ni * 8 + b_row) * KSTRIDE + k16 * 16 + b_koff) * 2);
#pragma unroll
                for (int ni = 0; ni < 4; ni++)
#pragma unroll
                    for (int mi = 0; mi < 4; mi++)
                        mma_f16(acc[mi][ni], a[mi], bl[ni][0], bl[ni][1]);
            }
        }
        __syncthreads();
        if (c + 2 < 32) load_chunk(c + 2, buf);
    }

    const int gid = lane >> 2, tig = lane & 3;
#pragma unroll
    for (int mi = 0; mi < 4; mi++) {
#pragma unroll
        for (int half = 0; half < 2; half++) {
            const int m = m0 + wm * 64 + mi * 16 + gid + half * 8;
            const int bb = m >> 11, s = m & 2047;
#pragma unroll
            for (int ni = 0; ni < 4; ni++) {
                const int n = n0 + wn * 32 + ni * 8 + tig * 2;
                float c0 = acc[mi][ni][half * 2 + 0] + bias[n];
                float c1 = acc[mi][ni][half * 2 + 1] + bias[n + 1];
                const int h = n >> 6, d = n & 63;
                size_t o = (((size_t)bb * N_HEADS + h) * S_LEN + s) * DK + d;
                if (z == 0) {
                    *(__half2*)&g_Qf[o] = __floats2half2_rn(c0 * 0.125f, c1 * 0.125f);
                } else if (z == 1) {
                    c0 += kpe[((size_t)h * DK + d) * S_LEN + s];
                    c1 += kpe[((size_t)h * DK + d + 1) * S_LEN + s];
                    *(__half2*)&g_Kf[o] = __floats2half2_rn(c0, c1);
                } else {
                    *(__half2*)&g_Vf[o] = __floats2half2_rn(c0, c1);
                }
            }
        }
    }
}

// ======================= fp16 single-pass output projection =======================
#define OP_STAGE_B (2 * 128 * KSTRIDE * 2)   // 20480
__global__ __launch_bounds__(256)
void outproj_f16_kernel(const float* __restrict__ bo, float* __restrict__ out_final)
{
    __shared__ __half sop[2][2 * 128 * KSTRIDE];

    const int m0 = blockIdx.y * BM;
    const int n0 = blockIdx.x * BN;
    const int tid = threadIdx.x;
    const int wid = tid >> 5, lane = tid & 31;
    const int wm = wid & 1, wn = wid >> 1;
    const uint32_t sbase = smem_u32(sop[0]);
    const int lrow = tid >> 1, lcp = tid & 1;

    auto load_chunk = [&](int kc, int buf) {
        const size_t ga = (size_t)(m0 + lrow) * D_MODEL + kc * 32 + lcp * 16;
        const size_t gb = (size_t)(n0 + lrow) * D_MODEL + kc * 32 + lcp * 16;
        const uint32_t so = sbase + buf * OP_STAGE_B + (lrow * KSTRIDE + lcp * 16) * 2;
        cp16(so, g_Of + ga);                      cp16(so + 16, g_Of + ga + 8);
        cp16(so + G_TILE_B, g_Wtf + gb);          cp16(so + G_TILE_B + 16, g_Wtf + gb + 8);
        asm volatile("cp.async.commit_group;" ::: "memory");
    };

    float acc[4][4][4];
#pragma unroll
    for (int i = 0; i < 4; i++)
#pragma unroll
        for (int j = 0; j < 4; j++)
#pragma unroll
            for (int c = 0; c < 4; c++) acc[i][j][c] = 0.f;

    load_chunk(0, 0);
    load_chunk(1, 1);

    const int a_row = (lane & 15), a_koff = (lane >> 4) * 8;
    const int b_row = (lane & 7),  b_koff = ((lane >> 3) & 1) * 8;

    for (int c = 0; c < 32; c++) {
        const int buf = c & 1;
        if (c < 31) asm volatile("cp.async.wait_group 1;" ::: "memory");
        else        asm volatile("cp.async.wait_group 0;" ::: "memory");
        __syncthreads();

        const uint32_t st = sbase + buf * OP_STAGE_B;
#pragma unroll
        for (int k16 = 0; k16 < 2; k16++) {
            uint32_t a[4][4], bf[4][2];
#pragma unroll
            for (int mi = 0; mi < 4; mi++)
                ldsm_x4(a[mi][0], a[mi][1], a[mi][2], a[mi][3],
                        st + ((wm * 64 + mi * 16 + a_row) * KSTRIDE + k16 * 16 + a_koff) * 2);
#pragma unroll
            for (int ni = 0; ni < 4; ni++)
                ldsm_x2(bf[ni][0], bf[ni][1],
                        st + G_TILE_B + ((wn * 32 + ni * 8 + b_row) * KSTRIDE + k16 * 16 + b_koff) * 2);
#pragma unroll
            for (int ni = 0; ni < 4; ni++)
#pragma unroll
                for (int mi = 0; mi < 4; mi++)
                    mma_f16(acc[mi][ni], a[mi], bf[ni][0], bf[ni][1]);
        }
        __syncthreads();
        if (c + 2 < 32) load_chunk(c + 2, buf);
    }

    const int gid = lane >> 2, tig = lane & 3;
#pragma unroll
    for (int mi = 0; mi < 4; mi++) {
#pragma unroll
        for (int half = 0; half < 2; half++) {
            const int m = m0 + wm * 64 + mi * 16 + gid + half * 8;
#pragma unroll
            for (int ni = 0; ni < 4; ni++) {
                const int n = n0 + wn * 32 + ni * 8 + tig * 2;
                *(float2*)&out_final[(size_t)m * D_MODEL + n] =
                    make_float2(acc[mi][ni][half * 2 + 0] + bo[n],
                                acc[mi][ni][half * 2 + 1] + bo[n + 1]);
            }
        }
    }
}

// ======================= fp16 flash attention, 2-way split-K, compact smem =======================
// smem: K double-buffer [0, 18432) + V double-buffer [18432, 36864) = 36864 B total.
// Q is staged through the K region before the KV pipeline starts (recycled after regs load).
#define AT_KSTR 72
#define FK_OFF  0
#define FV_OFF  18432
#define ATTN_SMEM5 36864
#define SPLIT_TILES 16

__global__ __launch_bounds__(256, 2)
void attn_mma_kernel()
{
    extern __shared__ char smc[];
    const uint32_t base = smem_u32(smc);

    const int tid = threadIdx.x;
    const int wid = tid >> 5, lane = tid & 31;
    const int q0 = blockIdx.x * 128;
    const int h = blockIdx.y;
    const int bz = blockIdx.z >> 1, sp = blockIdx.z & 1;
    const int bh = bz * N_HEADS + h;
    const int T0 = sp * SPLIT_TILES;

    const int a_row = (lane & 15), a_koff = (lane >> 4) * 8;
    const int b_row4 = (lane & 7) + ((lane >> 4) << 3);
    const int b_koff4 = ((lane >> 3) & 1) * 8;
    const int t_row = (lane & 7) + (((lane >> 3) & 1) << 3);
    const int t_col8 = (lane >> 4) * 8;
    const int gid = lane >> 2, tig = lane & 3;

    // ---- stage Q through the K region (recycled afterwards) ----
    uint32_t qf[4][4];
    {
#pragma unroll
        for (int it = 0; it < 4; it++) {
            int idx = tid + it * 256;
            int row = idx >> 3, cp = idx & 7;
            cp16(base + FK_OFF + (row * AT_KSTR + cp * 8) * 2,
                 g_Qf + ((size_t)bh * S_LEN + q0 + row) * DK + cp * 8);
        }
        asm volatile("cp.async.commit_group;" ::: "memory");
        asm volatile("cp.async.wait_group 0;" ::: "memory");
        __syncthreads();
#pragma unroll
        for (int k16 = 0; k16 < 4; k16++)
            ldsm_x4(qf[k16][0], qf[k16][1], qf[k16][2], qf[k16][3],
                    base + FK_OFF + ((wid * 16 + a_row) * AT_KSTR + k16 * 16 + a_koff) * 2);
        __syncthreads();   // Q consumed into registers; K region free for pipeline
    }

    auto load_kv = [&](int T, int bufx) {
        const int t0 = T * 64;
#pragma unroll
        for (int hf = 0; hf < 2; hf++) {
            int rem = tid + hf * 256;
            int row = rem >> 3, cp = rem & 7;
            cp16(base + FK_OFF + bufx * 9216 + (row * AT_KSTR + cp * 8) * 2,
                 g_Kf + ((size_t)bh * S_LEN + t0 + row) * DK + cp * 8);
            cp16(base + FV_OFF + bufx * 9216 + (row * AT_KSTR + cp * 8) * 2,
                 g_Vf + ((size_t)bh * S_LEN + t0 + row) * DK + cp * 8);
        }
        asm volatile("cp.async.commit_group;" ::: "memory");
    };

    float oacc[8][4];
#pragma unroll
    for (int ni = 0; ni < 8; ni++)
#pragma unroll
        for (int c = 0; c < 4; c++) oacc[ni][c] = 0.f;
    float m0 = -1e30f, m1 = -1e30f, l0 = 0.f, l1 = 0.f;

    load_kv(T0, 0);

#pragma unroll 1
    for (int Ti = 0; Ti < SPLIT_TILES; Ti++) {
        const int buf = Ti & 1;
        asm volatile("cp.async.wait_group 0;" ::: "memory");
        __syncthreads();
        if (Ti + 1 < SPLIT_TILES) load_kv(T0 + Ti + 1, buf ^ 1);

        const uint32_t kb = base + FK_OFF + buf * 9216;
        const uint32_t vb = base + FV_OFF + buf * 9216;

        // ---- QK^T (fp16) ----
        float sacc[8][4];
#pragma unroll
        for (int ni = 0; ni < 8; ni++)
#pragma unroll
            for (int c = 0; c < 4; c++) sacc[ni][c] = 0.f;

#pragma unroll
        for (int kd = 0; kd < 4; kd++) {
            uint32_t kf[4][4];
#pragma unroll
            for (int np = 0; np < 4; np++)
                ldsm_x4(kf[np][0], kf[np][1], kf[np][2], kf[np][3],
                        kb + ((np * 16 + b_row4) * AT_KSTR + kd * 16 + b_koff4) * 2);
#pragma unroll
            for (int np = 0; np < 4; np++) {
                mma_f16(sacc[2 * np],     qf[kd], kf[np][0], kf[np][1]);
                mma_f16(sacc[2 * np + 1], qf[kd], kf[np][2], kf[np][3]);
            }
        }

        // ---- register softmax ----
        float mx0 = -1e30f, mx1 = -1e30f;
#pragma unroll
        for (int ni = 0; ni < 8; ni++) {
            mx0 = fmaxf(mx0, fmaxf(sacc[ni][0], sacc[ni][1]));
            mx1 = fmaxf(mx1, fmaxf(sacc[ni][2], sacc[ni][3]));
        }
        mx0 = fmaxf(mx0, __shfl_xor_sync(0xffffffffu, mx0, 1));
        mx0 = fmaxf(mx0, __shfl_xor_sync(0xffffffffu, mx0, 2));
        mx1 = fmaxf(mx1, __shfl_xor_sync(0xffffffffu, mx1, 1));
        mx1 = fmaxf(mx1, __shfl_xor_sync(0xffffffffu, mx1, 2));

        const float mn0 = fmaxf(m0, mx0), mn1 = fmaxf(m1, mx1);
        const float cr0 = __expf(m0 - mn0), cr1 = __expf(m1 - mn1);
        m0 = mn0; m1 = mn1;

        float s0 = 0.f, s1 = 0.f;
#pragma unroll
        for (int ni = 0; ni < 8; ni++) {
            sacc[ni][0] = __expf(sacc[ni][0] - mn0);
            sacc[ni][1] = __expf(sacc[ni][1] - mn0);
            sacc[ni][2] = __expf(sacc[ni][2] - mn1);
            sacc[ni][3] = __expf(sacc[ni][3] - mn1);
            s0 += sacc[ni][0] + sacc[ni][1];
            s1 += sacc[ni][2] + sacc[ni][3];
        }
        s0 += __shfl_xor_sync(0xffffffffu, s0, 1);
        s0 += __shfl_xor_sync(0xffffffffu, s0, 2);
        s1 += __shfl_xor_sync(0xffffffffu, s1, 1);
        s1 += __shfl_xor_sync(0xffffffffu, s1, 2);
        l0 = l0 * cr0 + s0;
        l1 = l1 * cr1 + s1;

#pragma unroll
        for (int ni = 0; ni < 8; ni++) {
            oacc[ni][0] *= cr0; oacc[ni][1] *= cr0;
            oacc[ni][2] *= cr1; oacc[ni][3] *= cr1;
        }

        // ---- P fragments ----
        uint32_t pf[4][4];
#pragma unroll
        for (int kt = 0; kt < 4; kt++) {
            const float* e0 = sacc[2 * kt];
            const float* e1 = sacc[2 * kt + 1];
            pf[kt][0] = pack_h2(e0[0], e0[1]);
            pf[kt][1] = pack_h2(e0[2], e0[3]);
            pf[kt][2] = pack_h2(e1[0], e1[1]);
            pf[kt][3] = pack_h2(e1[2], e1[3]);
        }

        // ---- PV (V row-major via ldmatrix.trans) ----
#pragma unroll
        for (int kt = 0; kt < 4; kt++) {
            uint32_t vf[4][4];
#pragma unroll
            for (int np = 0; np < 4; np++)
                ldsm_x4_t(vf[np][0], vf[np][1], vf[np][2], vf[np][3],
                          vb + ((kt * 16 + t_row) * AT_KSTR + np * 16 + t_col8) * 2);
#pragma unroll
            for (int np = 0; np < 4; np++) {
                mma_f16(oacc[2 * np],     pf[kt], vf[np][0], vf[np][1]);
                mma_f16(oacc[2 * np + 1], pf[kt], vf[np][2], vf[np][3]);
            }
        }
    }

    // ---- epilogue ----
#pragma unroll
    for (int hf = 0; hf < 2; hf++) {
        const int s = q0 + wid * 16 + gid + hf * 8;
        const size_t row = (size_t)bh * S_LEN + s;
#pragma unroll
        for (int ni = 0; ni < 8; ni++) {
            const int d = ni * 8 + tig * 2;
            *(float2*)&g_Opart[sp][row * DK + d] =
                make_float2(oacc[ni][hf * 2 + 0], oacc[ni][hf * 2 + 1]);
        }
        if (tig == 0)
            g_MLpart[sp][row] = make_float2(hf ? m1 : m0, hf ? l1 : l0);
    }
}

// combine the two split-K halves -> fp16 attention output
__global__ __launch_bounds__(256) void attn_combine_kernel()
{
    size_t idx = ((size_t)blockIdx.x * 256 + threadIdx.x) * 4;
    size_t r = idx >> 6;
    int d = (int)(idx & 63);
    float2 ml0 = g_MLpart[0][r], ml1 = g_MLpart[1][r];
    float m = fmaxf(ml0.x, ml1.x);
    float c0 = __expf(ml0.x - m), c1 = __expf(ml1.x - m);
    float inv = 1.f / (c0 * ml0.y + c1 * ml1.y);
    float4 o0 = *(float4*)&g_Opart[0][idx];
    float4 o1 = *(float4*)&g_Opart[1][idx];
    float v0 = (c0 * o0.x + c1 * o1.x) * inv;
    float v1 = (c0 * o0.y + c1 * o1.y) * inv;
    float v2 = (c0 * o0.z + c1 * o1.z) * inv;
    float v3 = (c0 * o0.w + c1 * o1.w) * inv;

    int bz = (int)(r / (N_HEADS * S_LEN));
    int h  = (int)((r / S_LEN) % N_HEADS);
    int s  = (int)(r % S_LEN);
    size_t o = ((size_t)bz * S_LEN + s) * D_MODEL + h * DK + d;

    *(__half2*)&g_Of[o]     = __floats2half2_rn(v0, v1);
    *(__half2*)&g_Of[o + 2] = __floats2half2_rn(v2, v3);
}

// =====================================================================
extern "C" void kernel_launch(void* const* d_in, const int* in_sizes, int n_in,
                              void* d_out, int out_size)
{
    const float* q   = (const float*)d_in[0];
    const float* k   = (const float*)d_in[1];
    const float* v   = (const float*)d_in[2];
    const float* kpe = (const float*)d_in[3];
    const float* Wq  = (const float*)d_in[4];
    const float* bq  = (const float*)d_in[5];
    const float* Wk  = (const float*)d_in[6];
    const float* bk  = (const float*)d_in[7];
    const float* Wv  = (const float*)d_in[8];
    const float* bv  = (const float*)d_in[9];
    const float* Wo  = (const float*)d_in[10];
    const float* bo  = (const float*)d_in[11];
    float* out = (float*)d_out;

    cudaFuncSetAttribute(attn_mma_kernel, cudaFuncAttributeMaxDynamicSharedMemorySize,
                         ATTN_SMEM5);
    cudaFuncSetAttribute(attn_mma_kernel, cudaFuncAttributePreferredSharedMemoryCarveout,
                         cudaSharedmemCarveoutMaxShared);
    cudaFuncSetAttribute(gemm_f16_kernel, cudaFuncAttributeMaxDynamicSharedMemorySize,
                         GEMM_SMEM);

    // prep
    dim3 gs(M_ROWS * D_MODEL / 1024, 3);
    cvt_qkv_kernel<<<gs, 256>>>(q, k, v);
    dim3 gw(32, 32, 4);
    splitW_kernel<<<gw, dim3(32, 8)>>>(Wq, Wk, Wv, Wo);

    // Q/K/V projections (fp16 2-pass)
    dim3 gp(D_MODEL / BN, M_ROWS / BM, 3);
    gemm_f16_kernel<<<gp, 256, GEMM_SMEM>>>(kpe, bq, bk, bv);

    // attention (fp16 tensor cores, 2 CTAs/SM via compact smem, 2-way split-K)
    dim3 ga(S_LEN / 128, N_HEADS, B_SIZE * 2);
    attn_mma_kernel<<<ga, 256, ATTN_SMEM5>>>();
    attn_combine_kernel<<<BHS * DK / 1024, 256>>>();

    // output projection (fp16 single pass)
    dim3 go(D_MODEL / BN, M_ROWS / BM, 1);
    outproj_f16_kernel<<<go, 256>>>(bo, out);
}